// round 15
// baseline (speedup 1.0000x reference)
#include <cuda_runtime.h>
#include <math.h>

#define NTA 1024   // ab kernel threads (32 warps)
#define NTG 256    // gather kernel threads
#define RB  16     // rows (classes/codes) per ab block
#define AP  132    // smem activation pitch (floats)

struct Params {
  const int*   obs;
  const float *embed, *W1, *b1, *W2, *b2, *W3, *b3, *Wp, *bp, *codebook;
  const float *Wa, *ba, *Ws, *bs, *Wc1, *bc1, *Wc2, *bc2, *Wc3, *bc3, *Wc4, *bc4;
  float *out_actor, *out_scale, *out_critic, *out_loss, *out_idx;
  int NC, VQN, nClsBlk, B, gtiles;
};

// Device-global scratch (no allocation allowed)
__device__ int      g_idx_cls[1024];
__device__ float    g_loss_cls[1024];
__device__ float    g_tbl_actor[512 * 128];
__device__ float    g_tbl_scale[512 * 128];
__device__ float    g_tbl_crit[512];
__device__ float    g_partials[1024];
__device__ unsigned g_ticket;

struct SmemAB {
  float A[RB][AP];          // 8.4 KB
  float Bb[RB][AP];         // 8.4 KB
  float part[3][RB][AP];    // 25.3 KB k-quarter partials
  float dist[RB][512];      // 32 KB
  float znorm[RB];
};                          // ~75 KB

__device__ __forceinline__ float sigf(float x) { return 1.0f / (1.0f + expf(-x)); }

// ---------------- packed f32x2 helpers ----------------
__device__ __forceinline__ unsigned long long pack_dup(float a) {
  unsigned long long d;
  const unsigned ai = __float_as_uint(a);
  asm("mov.b64 %0, {%1, %1};" : "=l"(d) : "r"(ai));
  return d;
}
__device__ __forceinline__ void fma2(unsigned long long& d, unsigned long long a,
                                     unsigned long long b) {
  asm("fma.rn.f32x2 %0, %1, %2, %0;" : "+l"(d) : "l"(a), "l"(b));
}
__device__ __forceinline__ float lo32(unsigned long long v) {
  return __uint_as_float((unsigned)(v & 0xffffffffull));
}
__device__ __forceinline__ float hi32(unsigned long long v) {
  return __uint_as_float((unsigned)(v >> 32));
}
__device__ __forceinline__ float comp4(const float4& v, int j) {
  return j == 0 ? v.x : j == 1 ? v.y : j == 2 ? v.z : v.w;
}

// ---- 16-row GEMM layer, 32 warps: (kq x column-eighth) warp tiling ----
// warp: kq = warp>>3 (k-quarter), ce = warp&7 (column eighth).
// lane: slot = lane&3 (float4 col in eighth), rg = lane>>2 (rows 2rg,2rg+1).
// Per-column k-quarter partials and combine order identical to the proven
// NTA=512 kernel -> z / tables bit-identical.
// ACT: 0 linear, 1 relu, 2 sigmoid, 3 sigmoid+1e-8
template<int K, int N, int ACT>
__device__ __forceinline__ void layerY(const float (*__restrict__ in)[AP],
                                       const float* __restrict__ wg,
                                       const float* __restrict__ bias_g,
                                       float (*__restrict__ outs)[AP],
                                       float* __restrict__ outg, int grow0,
                                       SmemAB& sm)
{
  const int tid = threadIdx.x, warp = tid >> 5, lane = tid & 31;
  const int kq = warp >> 3, ce = warp & 7;
  constexpr int NG  = N / 4;      // float4 per output row
  constexpr int EPC = NG / 8;     // float4 slots per column-eighth
  const int slot = lane & 3, rg = lane >> 2;
  const int c4 = ce * EPC + slot; // this lane's float4 column
  const int r0 = rg * 2;          // this lane's 2 rows
  const bool active = slot < EPC;

  unsigned long long acc01[2], acc23[2];  // per row: col pairs (c0,c1),(c2,c3)
  acc01[0] = acc01[1] = acc23[0] = acc23[1] = 0ull;

  if (active) {
    const ulonglong2* w2 = reinterpret_cast<const ulonglong2*>(wg) + c4;
    const int kbeg = kq * (K / 4), kend = kbeg + (K / 4);
    #pragma unroll 4
    for (int k = kbeg; k < kend; k += 4) {
      float4 a[2];
      a[0] = *reinterpret_cast<const float4*>(&in[r0][k]);
      a[1] = *reinterpret_cast<const float4*>(&in[r0 + 1][k]);
      ulonglong2 w[4];
      #pragma unroll
      for (int j = 0; j < 4; j++) w[j] = __ldg(&w2[(size_t)(k + j) * NG]);
      #pragma unroll
      for (int j = 0; j < 4; j++) {
        #pragma unroll
        for (int r = 0; r < 2; r++) {
          const unsigned long long aa = pack_dup(comp4(a[r], j));
          fma2(acc01[r], aa, w[j].x);
          fma2(acc23[r], aa, w[j].y);
        }
      }
    }
  }
  if (kq > 0 && active) {
    #pragma unroll
    for (int r = 0; r < 2; r++) {
      const float4 o = make_float4(lo32(acc01[r]), hi32(acc01[r]),
                                   lo32(acc23[r]), hi32(acc23[r]));
      *reinterpret_cast<float4*>(&sm.part[kq - 1][r0 + r][c4 * 4]) = o;
    }
  }
  __syncthreads();
  if (kq == 0 && active) {
    const float4 bb = __ldg(reinterpret_cast<const float4*>(bias_g) + c4);
    #pragma unroll
    for (int r = 0; r < 2; r++) {
      const float4 p1 = *reinterpret_cast<const float4*>(&sm.part[0][r0 + r][c4 * 4]);
      const float4 p2 = *reinterpret_cast<const float4*>(&sm.part[1][r0 + r][c4 * 4]);
      const float4 p3 = *reinterpret_cast<const float4*>(&sm.part[2][r0 + r][c4 * 4]);
      const float a0 = lo32(acc01[r]), a1 = hi32(acc01[r]);
      const float a2 = lo32(acc23[r]), a3 = hi32(acc23[r]);
      float v[4] = {((a0 + p1.x) + p2.x) + p3.x + bb.x,
                    ((a1 + p1.y) + p2.y) + p3.y + bb.y,
                    ((a2 + p1.z) + p2.z) + p3.z + bb.z,
                    ((a3 + p1.w) + p2.w) + p3.w + bb.w};
      #pragma unroll
      for (int j = 0; j < 4; j++) {
        if (ACT == 1) v[j] = v[j] > 0.f ? v[j] : 0.f;
        if (ACT == 2 || ACT == 3) v[j] = sigf(v[j]);
        if (ACT == 3) v[j] += 1e-8f;
      }
      const float4 o = make_float4(v[0], v[1], v[2], v[3]);
      if (outs) *reinterpret_cast<float4*>(&outs[r0 + r][c4 * 4]) = o;
      if (outg)
        reinterpret_cast<float4*>(outg)[(size_t)(grow0 + r0 + r) * NG + c4] = o;
    }
  }
  __syncthreads();
}

__global__ void __launch_bounds__(NTA, 1) acsq_ab(Params p)
{
  extern __shared__ char smraw[];
  SmemAB& sm = *reinterpret_cast<SmemAB*>(smraw);
  const int tid = threadIdx.x;

  if ((int)blockIdx.x < p.nClsBlk) {
    // ================= CLASS PATH: 16 classes =================
    const int c0 = blockIdx.x * RB;

    if (tid < RB * 32) {   // embed gather: 16 rows x 32 float4
      const int r = tid >> 5, col = tid & 31, cls = c0 + r;
      float4 v = make_float4(0.f, 0.f, 0.f, 0.f);
      if (cls < p.NC)
        v = __ldg(reinterpret_cast<const float4*>(p.embed + (size_t)cls * 128) + col);
      reinterpret_cast<float4*>(sm.A[r])[col] = v;
    }
    __syncthreads();

    layerY<128, 128, 1>(sm.A,  p.W1, p.b1, sm.Bb, nullptr, 0, sm);
    layerY<128, 128, 1>(sm.Bb, p.W2, p.b2, sm.A,  nullptr, 0, sm);
    layerY<128, 128, 1>(sm.A,  p.W3, p.b3, sm.Bb, nullptr, 0, sm);
    layerY<128, 64, 0>(sm.Bb,  p.Wp, p.bp, sm.A,  nullptr, 0, sm);
    // z in A[:,0:64]
    if (tid < RB) {
      float s = 0.f;
      #pragma unroll
      for (int k = 0; k < 64; k++) s = fmaf(sm.A[tid][k], sm.A[tid][k], s);
      sm.znorm[tid] = s;
    }
    __syncthreads();

    // ---- VQ: 1024 threads = 512 codes x 2 row-halves ----
    {
      const int cc = tid & 511;
      const int rh = tid >> 9;          // 0 or 1
      if (cc < p.VQN) {
        ulonglong2 cb[16];
        const ulonglong2* cp =
            reinterpret_cast<const ulonglong2*>(p.codebook + (size_t)cc * 64);
        #pragma unroll
        for (int q = 0; q < 16; q++) cb[q] = __ldg(cp + q);
        unsigned long long cn2 = 0ull;
        #pragma unroll
        for (int q = 0; q < 16; q++) { fma2(cn2, cb[q].x, cb[q].x); fma2(cn2, cb[q].y, cb[q].y); }
        const float cn = lo32(cn2) + hi32(cn2);
        const int rbeg = rh * (RB / 2);
        #pragma unroll
        for (int rr = 0; rr < RB / 2; rr++) {
          const int r = rbeg + rr;
          const ulonglong2* A2 = reinterpret_cast<const ulonglong2*>(sm.A[r]);
          unsigned long long dot2 = 0ull;
          #pragma unroll
          for (int q = 0; q < 16; q++) {
            const ulonglong2 a = A2[q];           // broadcast LDS.128
            fma2(dot2, a.x, cb[q].x);
            fma2(dot2, a.y, cb[q].y);
          }
          const float dot = lo32(dot2) + hi32(dot2);
          sm.dist[r][cc] = sm.znorm[r] - 2.f * dot + cn;
        }
      }
    }
    __syncthreads();

    // ---- argmin per row (warps 0..15), lexicographic (d, idx) ----
    const int warp = tid >> 5, lane = tid & 31;
    if (warp < RB) {
      const int r = warp;
      float best = 3.4e38f; int bi = 0;
      for (int cc = lane; cc < p.VQN; cc += 32) {
        const float d = sm.dist[r][cc];
        if (d < best) { best = d; bi = cc; }
      }
      #pragma unroll
      for (int o = 16; o; o >>= 1) {
        const float ob = __shfl_down_sync(0xffffffffu, best, o);
        const int   oi = __shfl_down_sync(0xffffffffu, bi,   o);
        if (ob < best || (ob == best && oi < bi)) { best = ob; bi = oi; }
      }
      bi = __shfl_sync(0xffffffffu, bi, 0);
      float ls = 0.f;
      for (int k = lane; k < 64; k += 32) {
        const float dq = __ldg(p.codebook + (size_t)bi * 64 + k) - sm.A[r][k];
        ls = fmaf(dq, dq, ls);
      }
      #pragma unroll
      for (int o = 16; o; o >>= 1) ls += __shfl_down_sync(0xffffffffu, ls, o);
      if (lane == 0 && c0 + r < p.NC) {
        g_idx_cls[c0 + r]  = bi;
        g_loss_cls[c0 + r] = ls;
      }
    }
  } else {
    // ================= HEAD PATH: 16 codes =================
    const int q0 = ((int)blockIdx.x - p.nClsBlk) * RB;

    if (tid < RB * 16) {     // gather 16 codebook rows
      const int r = tid >> 4, col = tid & 15;
      reinterpret_cast<float4*>(sm.A[r])[col] =
          __ldg(reinterpret_cast<const float4*>(p.codebook + (size_t)(q0 + r) * 64) + col);
    }
    __syncthreads();

    layerY<64, 128, 2>(sm.A,  p.Wa,  p.ba,  nullptr, g_tbl_actor, q0, sm);
    layerY<64, 128, 3>(sm.A,  p.Ws,  p.bs,  nullptr, g_tbl_scale, q0, sm);
    layerY<64, 128, 2>(sm.A,  p.Wc1, p.bc1, sm.Bb,   nullptr, 0, sm);
    layerY<128, 128, 2>(sm.Bb, p.Wc2, p.bc2, sm.A,   nullptr, 0, sm);
    layerY<128, 32, 2>(sm.A,  p.Wc3, p.bc3, sm.Bb,   nullptr, 0, sm);

    if (tid < RB) {
      float s = __ldg(p.bc4);
      #pragma unroll
      for (int k = 0; k < 32; k++) s = fmaf(sm.Bb[tid][k], __ldg(p.Wc4 + k), s);
      g_tbl_crit[q0 + tid] = s;
    }
  }
}

// ==== gather: 1024 blocks = 512 row-tiles x {actor, scale} ====
// Actor blocks additionally write idx/critic and the loss partial for their
// tile (same 256-row grouping as the proven kernel -> loss bit-identical).
__global__ void __launch_bounds__(NTG) acsq_gather(Params p, float scale)
{
  __shared__ int   codes[NTG];
  __shared__ float red[8];
  __shared__ float s[NTG];
  __shared__ bool  lastblk;
  const int tid = threadIdx.x;
  const int tbl = blockIdx.x & 1;                // 0 = actor, 1 = scale
  const int rt  = blockIdx.x >> 1;               // row tile
  const size_t row0 = (size_t)rt * NTG;
  const size_t b = row0 + tid;

  if (tid == 0) lastblk = false;

  float lp = 0.f;
  int code = 0;
  if (b < (size_t)p.B) {
    const int o = p.obs[b];
    code = g_idx_cls[o];
    if (tbl == 0) {
      lp = g_loss_cls[o];
      p.out_idx[b]    = (float)code;
      p.out_critic[b] = g_tbl_crit[code];
    }
  }
  codes[tid] = code;

  if (tbl == 0) {
    #pragma unroll
    for (int o = 16; o; o >>= 1) lp += __shfl_down_sync(0xffffffffu, lp, o);
    if ((tid & 31) == 0) red[tid >> 5] = lp;
  }
  __syncthreads();
  if (tbl == 0 && tid == 0) {
    float t = 0.f;
    #pragma unroll
    for (int w = 0; w < 8; w++) t += red[w];
    g_partials[rt] = t;
    __threadfence();
    lastblk = (atomicAdd(&g_ticket, 1u) == (unsigned)(p.gtiles - 1));
  }

  const float4* ta = reinterpret_cast<const float4*>(tbl ? g_tbl_scale : g_tbl_actor);
  float4* od = reinterpret_cast<float4*>(tbl ? p.out_scale : p.out_actor);
  __syncthreads();
  #pragma unroll 4
  for (int i = tid; i < NTG * 32; i += NTG) {
    const int r = i >> 5, cc = i & 31;
    if (row0 + r < (size_t)p.B) {
      const int cd = codes[r];
      od[(row0 + r) * 32 + cc] = ta[cd * 32 + cc];
    }
  }

  if (lastblk) {
    float v = 0.f;
    for (int i = tid; i < p.gtiles; i += NTG) v += g_partials[i];  // fixed order
    s[tid] = v;
    __syncthreads();
    for (int o = NTG / 2; o > 0; o >>= 1) {
      if (tid < o) s[tid] += s[tid + o];
      __syncthreads();
    }
    if (tid == 0) { *p.out_loss = s[0] * scale; g_ticket = 0u; }
  }
}

extern "C" void kernel_launch(void* const* d_in, const int* in_sizes, int n_in,
                              void* d_out, int out_size)
{
  Params p;
  p.obs      = (const int*)d_in[0];
  p.embed    = (const float*)d_in[1];
  p.W1  = (const float*)d_in[2];  p.b1  = (const float*)d_in[3];
  p.W2  = (const float*)d_in[4];  p.b2  = (const float*)d_in[5];
  p.W3  = (const float*)d_in[6];  p.b3  = (const float*)d_in[7];
  p.Wp  = (const float*)d_in[8];  p.bp  = (const float*)d_in[9];
  p.codebook = (const float*)d_in[10];
  p.Wa  = (const float*)d_in[11]; p.ba  = (const float*)d_in[12];
  p.Ws  = (const float*)d_in[13]; p.bs  = (const float*)d_in[14];
  p.Wc1 = (const float*)d_in[15]; p.bc1 = (const float*)d_in[16];
  p.Wc2 = (const float*)d_in[17]; p.bc2 = (const float*)d_in[18];
  p.Wc3 = (const float*)d_in[19]; p.bc3 = (const float*)d_in[20];
  p.Wc4 = (const float*)d_in[21]; p.bc4 = (const float*)d_in[22];

  const int B   = in_sizes[0];
  const int NC  = in_sizes[1] / 128;   // embed is [NC, 128]
  const int VQN = in_sizes[10] / 64;   // codebook is [VQN, 64]
  p.B = B; p.NC = NC; p.VQN = VQN;
  p.nClsBlk = (NC + RB - 1) / RB;      // 63
  p.gtiles  = (B + NTG - 1) / NTG;     // 512

  float* out = (float*)d_out;
  p.out_actor  = out;                                  // [B,128]
  p.out_scale  = out + (size_t)B * 128;                // [B,128]
  p.out_critic = out + (size_t)2 * B * 128;            // [B]
  p.out_loss   = out + (size_t)2 * B * 128 + B;        // scalar
  p.out_idx    = out + (size_t)2 * B * 128 + B + 1;    // [B] as float

  const int headBlk = (VQN + RB - 1) / RB;             // 32
  cudaFuncSetAttribute(acsq_ab, cudaFuncAttributeMaxDynamicSharedMemorySize,
                       (int)sizeof(SmemAB));
  acsq_ab<<<p.nClsBlk + headBlk, NTA, sizeof(SmemAB)>>>(p);
  acsq_gather<<<p.gtiles * 2, NTG>>>(p, 1.25f / ((float)B * 64.f));
}

// round 16
// speedup vs baseline: 1.2732x; 1.2732x over previous
#include <cuda_runtime.h>
#include <math.h>

#define NTA 512    // ab kernel threads (16 warps) — R10 proven config
#define NTG 256    // gather kernel threads
#define RB  16     // rows (classes/codes) per ab block
#define AP  132    // smem activation pitch (floats)

struct Params {
  const int*   obs;
  const float *embed, *W1, *b1, *W2, *b2, *W3, *b3, *Wp, *bp, *codebook;
  const float *Wa, *ba, *Ws, *bs, *Wc1, *bc1, *Wc2, *bc2, *Wc3, *bc3, *Wc4, *bc4;
  float *out_actor, *out_scale, *out_critic, *out_loss, *out_idx;
  int NC, VQN, nClsBlk, B, gtiles;
};

// Device-global scratch (no allocation allowed)
__device__ int      g_idx_cls[1024];
__device__ float    g_loss_cls[1024];
__device__ float    g_tbl_actor[512 * 128];
__device__ float    g_tbl_scale[512 * 128];
__device__ float    g_tbl_crit[512];
__device__ float    g_partials[1024];
__device__ unsigned g_ticket;

struct SmemAB {
  float A[RB][AP];          // 8.4 KB
  float Bb[RB][AP];         // 8.4 KB
  float part[3][RB][AP];    // 25.3 KB k-quarter partials
  float dist[RB][512];      // 32 KB
  float znorm[RB];
};                          // ~75 KB

__device__ __forceinline__ float sigf(float x) { return 1.0f / (1.0f + expf(-x)); }

// ---------------- packed f32x2 helpers ----------------
__device__ __forceinline__ unsigned long long pack_dup(float a) {
  unsigned long long d;
  const unsigned ai = __float_as_uint(a);
  asm("mov.b64 %0, {%1, %1};" : "=l"(d) : "r"(ai));
  return d;
}
__device__ __forceinline__ void fma2(unsigned long long& d, unsigned long long a,
                                     unsigned long long b) {
  asm("fma.rn.f32x2 %0, %1, %2, %0;" : "+l"(d) : "l"(a), "l"(b));
}
__device__ __forceinline__ float lo32(unsigned long long v) {
  return __uint_as_float((unsigned)(v & 0xffffffffull));
}
__device__ __forceinline__ float hi32(unsigned long long v) {
  return __uint_as_float((unsigned)(v >> 32));
}
__device__ __forceinline__ float comp4(const float4& v, int j) {
  return j == 0 ? v.x : j == 1 ? v.y : j == 2 ? v.z : v.w;
}

// ---- 16-row GEMM layer; weights streamed DIRECTLY from global (L2-hot) ----
// warp w (16): kq = warp>>2 (k-quarter), cq = warp&3 (column quarter).
// lane: slot = lane&7 (float4 col in quarter), rg = lane>>3 (rows 4rg..4rg+3).
// FFMA2 paired across columns: per-column k-sum order unchanged (bit-exact).
// ACT: 0 linear, 1 relu, 2 sigmoid, 3 sigmoid+1e-8
template<int K, int N, int ACT>
__device__ __forceinline__ void layerW(const float (*__restrict__ in)[AP],
                                       const float* __restrict__ wg,
                                       const float* __restrict__ bias_g,
                                       float (*__restrict__ outs)[AP],
                                       float* __restrict__ outg, int grow0,
                                       SmemAB& sm)
{
  const int tid = threadIdx.x, warp = tid >> 5, lane = tid & 31;
  const int kq = warp >> 2, cq = warp & 3;
  constexpr int NG  = N / 4;      // float4 per output row
  constexpr int SPC = NG / 4;     // float4 slots per column-quarter
  const int slot = lane & 7, rg = lane >> 3;
  const int c4 = cq * SPC + slot; // this lane's float4 column
  const int r0 = rg * 4;          // this lane's 4 rows
  const bool active = slot < SPC;

  unsigned long long acc01[4], acc23[4];   // per row: col pairs (c0,c1),(c2,c3)
  #pragma unroll
  for (int r = 0; r < 4; r++) { acc01[r] = 0ull; acc23[r] = 0ull; }

  if (active) {
    const ulonglong2* w2 = reinterpret_cast<const ulonglong2*>(wg) + c4;
    const int kbeg = kq * (K / 4), kend = kbeg + (K / 4);
    #pragma unroll 2
    for (int k = kbeg; k < kend; k += 4) {
      float4 a[4];
      #pragma unroll
      for (int r = 0; r < 4; r++)
        a[r] = *reinterpret_cast<const float4*>(&in[r0 + r][k]);
      ulonglong2 w[4];
      #pragma unroll
      for (int j = 0; j < 4; j++) w[j] = __ldg(&w2[(size_t)(k + j) * NG]);
      #pragma unroll
      for (int j = 0; j < 4; j++) {
        #pragma unroll
        for (int r = 0; r < 4; r++) {
          const unsigned long long aa = pack_dup(comp4(a[r], j));
          fma2(acc01[r], aa, w[j].x);
          fma2(acc23[r], aa, w[j].y);
        }
      }
    }
  }
  if (kq > 0 && active) {
    #pragma unroll
    for (int r = 0; r < 4; r++) {
      const float4 o = make_float4(lo32(acc01[r]), hi32(acc01[r]),
                                   lo32(acc23[r]), hi32(acc23[r]));
      *reinterpret_cast<float4*>(&sm.part[kq - 1][r0 + r][c4 * 4]) = o;
    }
  }
  __syncthreads();
  if (kq == 0 && active) {
    const float4 bb = __ldg(reinterpret_cast<const float4*>(bias_g) + c4);
    #pragma unroll
    for (int r = 0; r < 4; r++) {
      const float4 p1 = *reinterpret_cast<const float4*>(&sm.part[0][r0 + r][c4 * 4]);
      const float4 p2 = *reinterpret_cast<const float4*>(&sm.part[1][r0 + r][c4 * 4]);
      const float4 p3 = *reinterpret_cast<const float4*>(&sm.part[2][r0 + r][c4 * 4]);
      const float a0 = lo32(acc01[r]), a1 = hi32(acc01[r]);
      const float a2 = lo32(acc23[r]), a3 = hi32(acc23[r]);
      float v[4] = {((a0 + p1.x) + p2.x) + p3.x + bb.x,
                    ((a1 + p1.y) + p2.y) + p3.y + bb.y,
                    ((a2 + p1.z) + p2.z) + p3.z + bb.z,
                    ((a3 + p1.w) + p2.w) + p3.w + bb.w};
      #pragma unroll
      for (int j = 0; j < 4; j++) {
        if (ACT == 1) v[j] = v[j] > 0.f ? v[j] : 0.f;
        if (ACT == 2 || ACT == 3) v[j] = sigf(v[j]);
        if (ACT == 3) v[j] += 1e-8f;
      }
      const float4 o = make_float4(v[0], v[1], v[2], v[3]);
      if (outs) *reinterpret_cast<float4*>(&outs[r0 + r][c4 * 4]) = o;
      if (outg)
        reinterpret_cast<float4*>(outg)[(size_t)(grow0 + r0 + r) * NG + c4] = o;
    }
  }
  __syncthreads();
}

__global__ void __launch_bounds__(NTA, 1) acsq_ab(Params p)
{
  extern __shared__ char smraw[];
  SmemAB& sm = *reinterpret_cast<SmemAB*>(smraw);
  const int tid = threadIdx.x;

  if ((int)blockIdx.x < p.nClsBlk) {
    // ================= CLASS PATH: 16 classes =================
    const int c0 = blockIdx.x * RB;

    {   // embed gather: 16 rows x 32 float4
      const int r = tid >> 5, col = tid & 31, cls = c0 + r;
      float4 v = make_float4(0.f, 0.f, 0.f, 0.f);
      if (cls < p.NC)
        v = __ldg(reinterpret_cast<const float4*>(p.embed + (size_t)cls * 128) + col);
      reinterpret_cast<float4*>(sm.A[r])[col] = v;
    }
    __syncthreads();

    layerW<128, 128, 1>(sm.A,  p.W1, p.b1, sm.Bb, nullptr, 0, sm);
    layerW<128, 128, 1>(sm.Bb, p.W2, p.b2, sm.A,  nullptr, 0, sm);
    layerW<128, 128, 1>(sm.A,  p.W3, p.b3, sm.Bb, nullptr, 0, sm);
    layerW<128, 64, 0>(sm.Bb,  p.Wp, p.bp, sm.A,  nullptr, 0, sm);
    // z in A[:,0:64]
    if (tid < RB) {
      float s = 0.f;
      #pragma unroll
      for (int k = 0; k < 64; k++) s = fmaf(sm.A[tid][k], sm.A[tid][k], s);
      sm.znorm[tid] = s;
    }
    __syncthreads();

    // ---- VQ distances: one thread per code; FFMA2 paired across k ----
    {
      const int cc = tid;
      if (cc < p.VQN) {
        ulonglong2 cb[16];
        const ulonglong2* cp =
            reinterpret_cast<const ulonglong2*>(p.codebook + (size_t)cc * 64);
        #pragma unroll
        for (int q = 0; q < 16; q++) cb[q] = __ldg(cp + q);
        unsigned long long cn2 = 0ull;
        #pragma unroll
        for (int q = 0; q < 16; q++) { fma2(cn2, cb[q].x, cb[q].x); fma2(cn2, cb[q].y, cb[q].y); }
        const float cn = lo32(cn2) + hi32(cn2);
        #pragma unroll
        for (int r = 0; r < RB; r++) {
          const ulonglong2* A2 = reinterpret_cast<const ulonglong2*>(sm.A[r]);
          unsigned long long dot2 = 0ull;
          #pragma unroll
          for (int q = 0; q < 16; q++) {
            const ulonglong2 a = A2[q];           // broadcast LDS.128
            fma2(dot2, a.x, cb[q].x);
            fma2(dot2, a.y, cb[q].y);
          }
          const float dot = lo32(dot2) + hi32(dot2);
          sm.dist[r][cc] = sm.znorm[r] - 2.f * dot + cn;
        }
      }
    }
    __syncthreads();

    // ---- argmin per row (warp r of 16), lexicographic (d, idx) ----
    const int warp = tid >> 5, lane = tid & 31;
    {
      const int r = warp;
      float best = 3.4e38f; int bi = 0;
      for (int cc = lane; cc < p.VQN; cc += 32) {
        const float d = sm.dist[r][cc];
        if (d < best) { best = d; bi = cc; }
      }
      #pragma unroll
      for (int o = 16; o; o >>= 1) {
        const float ob = __shfl_down_sync(0xffffffffu, best, o);
        const int   oi = __shfl_down_sync(0xffffffffu, bi,   o);
        if (ob < best || (ob == best && oi < bi)) { best = ob; bi = oi; }
      }
      bi = __shfl_sync(0xffffffffu, bi, 0);
      float ls = 0.f;
      for (int k = lane; k < 64; k += 32) {
        const float dq = __ldg(p.codebook + (size_t)bi * 64 + k) - sm.A[r][k];
        ls = fmaf(dq, dq, ls);
      }
      #pragma unroll
      for (int o = 16; o; o >>= 1) ls += __shfl_down_sync(0xffffffffu, ls, o);
      if (lane == 0 && c0 + r < p.NC) {
        g_idx_cls[c0 + r]  = bi;
        g_loss_cls[c0 + r] = ls;
      }
    }
  } else {
    // ================= HEAD PATH: 16 codes =================
    const int q0 = ((int)blockIdx.x - p.nClsBlk) * RB;

    if (tid < RB * 16) {     // gather 16 codebook rows
      const int r = tid >> 4, col = tid & 15;
      reinterpret_cast<float4*>(sm.A[r])[col] =
          __ldg(reinterpret_cast<const float4*>(p.codebook + (size_t)(q0 + r) * 64) + col);
    }
    __syncthreads();

    layerW<64, 128, 2>(sm.A,  p.Wa,  p.ba,  nullptr, g_tbl_actor, q0, sm);
    layerW<64, 128, 3>(sm.A,  p.Ws,  p.bs,  nullptr, g_tbl_scale, q0, sm);
    layerW<64, 128, 2>(sm.A,  p.Wc1, p.bc1, sm.Bb,   nullptr, 0, sm);
    layerW<128, 128, 2>(sm.Bb, p.Wc2, p.bc2, sm.A,   nullptr, 0, sm);
    layerW<128, 32, 2>(sm.A,  p.Wc3, p.bc3, sm.Bb,   nullptr, 0, sm);

    if (tid < RB) {
      float s = __ldg(p.bc4);
      #pragma unroll
      for (int k = 0; k < 32; k++) s = fmaf(sm.Bb[tid][k], __ldg(p.Wc4 + k), s);
      g_tbl_crit[q0 + tid] = s;
    }
  }
}

// ==== gather (round-15 split version, measured 24.9 us): ====
// 1024 blocks = 512 row-tiles x {actor, scale}. Actor blocks also write
// idx/critic and the per-tile loss partial (same 256-row grouping as the
// proven kernel -> loss bit-identical).
__global__ void __launch_bounds__(NTG) acsq_gather(Params p, float scale)
{
  __shared__ int   codes[NTG];
  __shared__ float red[8];
  __shared__ float s[NTG];
  __shared__ bool  lastblk;
  const int tid = threadIdx.x;
  const int tbl = blockIdx.x & 1;                // 0 = actor, 1 = scale
  const int rt  = blockIdx.x >> 1;               // row tile
  const size_t row0 = (size_t)rt * NTG;
  const size_t b = row0 + tid;

  if (tid == 0) lastblk = false;

  float lp = 0.f;
  int code = 0;
  if (b < (size_t)p.B) {
    const int o = p.obs[b];
    code = g_idx_cls[o];
    if (tbl == 0) {
      lp = g_loss_cls[o];
      p.out_idx[b]    = (float)code;
      p.out_critic[b] = g_tbl_crit[code];
    }
  }
  codes[tid] = code;

  if (tbl == 0) {
    #pragma unroll
    for (int o = 16; o; o >>= 1) lp += __shfl_down_sync(0xffffffffu, lp, o);
    if ((tid & 31) == 0) red[tid >> 5] = lp;
  }
  __syncthreads();
  if (tbl == 0 && tid == 0) {
    float t = 0.f;
    #pragma unroll
    for (int w = 0; w < 8; w++) t += red[w];
    g_partials[rt] = t;
    __threadfence();
    lastblk = (atomicAdd(&g_ticket, 1u) == (unsigned)(p.gtiles - 1));
  }

  const float4* ta = reinterpret_cast<const float4*>(tbl ? g_tbl_scale : g_tbl_actor);
  float4* od = reinterpret_cast<float4*>(tbl ? p.out_scale : p.out_actor);
  __syncthreads();
  #pragma unroll 4
  for (int i = tid; i < NTG * 32; i += NTG) {
    const int r = i >> 5, cc = i & 31;
    if (row0 + r < (size_t)p.B) {
      const int cd = codes[r];
      od[(row0 + r) * 32 + cc] = ta[cd * 32 + cc];
    }
  }

  if (lastblk) {
    float v = 0.f;
    for (int i = tid; i < p.gtiles; i += NTG) v += g_partials[i];  // fixed order
    s[tid] = v;
    __syncthreads();
    for (int o = NTG / 2; o > 0; o >>= 1) {
      if (tid < o) s[tid] += s[tid + o];
      __syncthreads();
    }
    if (tid == 0) { *p.out_loss = s[0] * scale; g_ticket = 0u; }
  }
}

extern "C" void kernel_launch(void* const* d_in, const int* in_sizes, int n_in,
                              void* d_out, int out_size)
{
  Params p;
  p.obs      = (const int*)d_in[0];
  p.embed    = (const float*)d_in[1];
  p.W1  = (const float*)d_in[2];  p.b1  = (const float*)d_in[3];
  p.W2  = (const float*)d_in[4];  p.b2  = (const float*)d_in[5];
  p.W3  = (const float*)d_in[6];  p.b3  = (const float*)d_in[7];
  p.Wp  = (const float*)d_in[8];  p.bp  = (const float*)d_in[9];
  p.codebook = (const float*)d_in[10];
  p.Wa  = (const float*)d_in[11]; p.ba  = (const float*)d_in[12];
  p.Ws  = (const float*)d_in[13]; p.bs  = (const float*)d_in[14];
  p.Wc1 = (const float*)d_in[15]; p.bc1 = (const float*)d_in[16];
  p.Wc2 = (const float*)d_in[17]; p.bc2 = (const float*)d_in[18];
  p.Wc3 = (const float*)d_in[19]; p.bc3 = (const float*)d_in[20];
  p.Wc4 = (const float*)d_in[21]; p.bc4 = (const float*)d_in[22];

  const int B   = in_sizes[0];
  const int NC  = in_sizes[1] / 128;   // embed is [NC, 128]
  const int VQN = in_sizes[10] / 64;   // codebook is [VQN, 64]
  p.B = B; p.NC = NC; p.VQN = VQN;
  p.nClsBlk = (NC + RB - 1) / RB;      // 63
  p.gtiles  = (B + NTG - 1) / NTG;     // 512

  float* out = (float*)d_out;
  p.out_actor  = out;                                  // [B,128]
  p.out_scale  = out + (size_t)B * 128;                // [B,128]
  p.out_critic = out + (size_t)2 * B * 128;            // [B]
  p.out_loss   = out + (size_t)2 * B * 128 + B;        // scalar
  p.out_idx    = out + (size_t)2 * B * 128 + B + 1;    // [B] as float

  const int headBlk = (VQN + RB - 1) / RB;             // 32
  cudaFuncSetAttribute(acsq_ab, cudaFuncAttributeMaxDynamicSharedMemorySize,
                       (int)sizeof(SmemAB));
  acsq_ab<<<p.nClsBlk + headBlk, NTA, sizeof(SmemAB)>>>(p);
  acsq_gather<<<p.gtiles * 2, NTG>>>(p, 1.25f / ((float)B * 64.f));
}

// round 17
// speedup vs baseline: 1.3532x; 1.0628x over previous
#include <cuda_runtime.h>
#include <math.h>

#define NTA 512    // ab kernel threads (16 warps)
#define NTG 256    // gather kernel threads
#define RB  16     // rows (classes/codes) per ab block
#define AP  132    // smem activation pitch (floats)

struct Params {
  const int*   obs;
  const float *embed, *W1, *b1, *W2, *b2, *W3, *b3, *Wp, *bp, *codebook;
  const float *Wa, *ba, *Ws, *bs, *Wc1, *bc1, *Wc2, *bc2, *Wc3, *bc3, *Wc4, *bc4;
  float *out_actor, *out_scale, *out_critic, *out_loss, *out_idx;
  int NC, VQN, nClsBlk, B, gtiles;
};

// Device-global scratch (no allocation allowed)
__device__ int      g_idx_cls[1024];
__device__ float    g_loss_cls[1024];
__device__ float    g_tbl_actor[512 * 128];
__device__ float    g_tbl_scale[512 * 128];
__device__ float    g_tbl_crit[512];
__device__ float    g_partials[1024];
__device__ unsigned g_ticket;

struct SmemAB {
  float A[RB][AP];          // 8.4 KB
  float Bb[RB][AP];         // 8.4 KB
  float part[3][RB][AP];    // 25.3 KB k-quarter partials
  float dist[RB][512];      // 32 KB
  float znorm[RB];
};                          // ~75 KB

__device__ __forceinline__ float sigf(float x) { return 1.0f / (1.0f + expf(-x)); }

// ---------------- packed f32x2 helpers ----------------
__device__ __forceinline__ unsigned long long pack_dup(float a) {
  unsigned long long d;
  const unsigned ai = __float_as_uint(a);
  asm("mov.b64 %0, {%1, %1};" : "=l"(d) : "r"(ai));
  return d;
}
__device__ __forceinline__ void fma2(unsigned long long& d, unsigned long long a,
                                     unsigned long long b) {
  asm("fma.rn.f32x2 %0, %1, %2, %0;" : "+l"(d) : "l"(a), "l"(b));
}
__device__ __forceinline__ float lo32(unsigned long long v) {
  return __uint_as_float((unsigned)(v & 0xffffffffull));
}
__device__ __forceinline__ float hi32(unsigned long long v) {
  return __uint_as_float((unsigned)(v >> 32));
}
__device__ __forceinline__ float comp4(const float4& v, int j) {
  return j == 0 ? v.x : j == 1 ? v.y : j == 2 ? v.z : v.w;
}

// ---- 16-row GEMM layer; weights streamed DIRECTLY from global (L2-hot) ----
// warp w (16): kq = warp>>2 (k-quarter), cq = warp&3 (column quarter).
// lane: slot = lane&7 (float4 col in quarter), rg = lane>>3 (rows 4rg..4rg+3).
// DEEP UNROLL (8 k-groups) so ~32 weight LDG.128 are in flight per thread,
// hiding the ~250-cycle L2 latency that was the real ab bottleneck.
// FFMA2 paired across columns: per-column k-sum order unchanged (bit-exact).
// ACT: 0 linear, 1 relu, 2 sigmoid, 3 sigmoid+1e-8
template<int K, int N, int ACT>
__device__ __forceinline__ void layerW(const float (*__restrict__ in)[AP],
                                       const float* __restrict__ wg,
                                       const float* __restrict__ bias_g,
                                       float (*__restrict__ outs)[AP],
                                       float* __restrict__ outg, int grow0,
                                       SmemAB& sm)
{
  const int tid = threadIdx.x, warp = tid >> 5, lane = tid & 31;
  const int kq = warp >> 2, cq = warp & 3;
  constexpr int NG  = N / 4;      // float4 per output row
  constexpr int SPC = NG / 4;     // float4 slots per column-quarter
  const int slot = lane & 7, rg = lane >> 3;
  const int c4 = cq * SPC + slot; // this lane's float4 column
  const int r0 = rg * 4;          // this lane's 4 rows
  const bool active = slot < SPC;

  unsigned long long acc01[4], acc23[4];   // per row: col pairs (c0,c1),(c2,c3)
  #pragma unroll
  for (int r = 0; r < 4; r++) { acc01[r] = 0ull; acc23[r] = 0ull; }

  if (active) {
    const ulonglong2* w2 = reinterpret_cast<const ulonglong2*>(wg) + c4;
    const int kbeg = kq * (K / 4), kend = kbeg + (K / 4);
    #pragma unroll 8
    for (int k = kbeg; k < kend; k += 4) {
      float4 a[4];
      #pragma unroll
      for (int r = 0; r < 4; r++)
        a[r] = *reinterpret_cast<const float4*>(&in[r0 + r][k]);
      ulonglong2 w[4];
      #pragma unroll
      for (int j = 0; j < 4; j++) w[j] = __ldg(&w2[(size_t)(k + j) * NG]);
      #pragma unroll
      for (int j = 0; j < 4; j++) {
        #pragma unroll
        for (int r = 0; r < 4; r++) {
          const unsigned long long aa = pack_dup(comp4(a[r], j));
          fma2(acc01[r], aa, w[j].x);
          fma2(acc23[r], aa, w[j].y);
        }
      }
    }
  }
  if (kq > 0 && active) {
    #pragma unroll
    for (int r = 0; r < 4; r++) {
      const float4 o = make_float4(lo32(acc01[r]), hi32(acc01[r]),
                                   lo32(acc23[r]), hi32(acc23[r]));
      *reinterpret_cast<float4*>(&sm.part[kq - 1][r0 + r][c4 * 4]) = o;
    }
  }
  __syncthreads();
  if (kq == 0 && active) {
    const float4 bb = __ldg(reinterpret_cast<const float4*>(bias_g) + c4);
    #pragma unroll
    for (int r = 0; r < 4; r++) {
      const float4 p1 = *reinterpret_cast<const float4*>(&sm.part[0][r0 + r][c4 * 4]);
      const float4 p2 = *reinterpret_cast<const float4*>(&sm.part[1][r0 + r][c4 * 4]);
      const float4 p3 = *reinterpret_cast<const float4*>(&sm.part[2][r0 + r][c4 * 4]);
      const float a0 = lo32(acc01[r]), a1 = hi32(acc01[r]);
      const float a2 = lo32(acc23[r]), a3 = hi32(acc23[r]);
      float v[4] = {((a0 + p1.x) + p2.x) + p3.x + bb.x,
                    ((a1 + p1.y) + p2.y) + p3.y + bb.y,
                    ((a2 + p1.z) + p2.z) + p3.z + bb.z,
                    ((a3 + p1.w) + p2.w) + p3.w + bb.w};
      #pragma unroll
      for (int j = 0; j < 4; j++) {
        if (ACT == 1) v[j] = v[j] > 0.f ? v[j] : 0.f;
        if (ACT == 2 || ACT == 3) v[j] = sigf(v[j]);
        if (ACT == 3) v[j] += 1e-8f;
      }
      const float4 o = make_float4(v[0], v[1], v[2], v[3]);
      if (outs) *reinterpret_cast<float4*>(&outs[r0 + r][c4 * 4]) = o;
      if (outg)
        reinterpret_cast<float4*>(outg)[(size_t)(grow0 + r0 + r) * NG + c4] = o;
    }
  }
  __syncthreads();
}

__global__ void __launch_bounds__(NTA, 1) acsq_ab(Params p)
{
  extern __shared__ char smraw[];
  SmemAB& sm = *reinterpret_cast<SmemAB*>(smraw);
  const int tid = threadIdx.x;

  if ((int)blockIdx.x < p.nClsBlk) {
    // ================= CLASS PATH: 16 classes =================
    const int c0 = blockIdx.x * RB;

    {   // embed gather: 16 rows x 32 float4
      const int r = tid >> 5, col = tid & 31, cls = c0 + r;
      float4 v = make_float4(0.f, 0.f, 0.f, 0.f);
      if (cls < p.NC)
        v = __ldg(reinterpret_cast<const float4*>(p.embed + (size_t)cls * 128) + col);
      reinterpret_cast<float4*>(sm.A[r])[col] = v;
    }
    __syncthreads();

    layerW<128, 128, 1>(sm.A,  p.W1, p.b1, sm.Bb, nullptr, 0, sm);
    layerW<128, 128, 1>(sm.Bb, p.W2, p.b2, sm.A,  nullptr, 0, sm);
    layerW<128, 128, 1>(sm.A,  p.W3, p.b3, sm.Bb, nullptr, 0, sm);
    layerW<128, 64, 0>(sm.Bb,  p.Wp, p.bp, sm.A,  nullptr, 0, sm);
    // z in A[:,0:64]
    if (tid < RB) {
      float s = 0.f;
      #pragma unroll
      for (int k = 0; k < 64; k++) s = fmaf(sm.A[tid][k], sm.A[tid][k], s);
      sm.znorm[tid] = s;
    }
    __syncthreads();

    // ---- VQ distances: one thread per code; FFMA2 paired across k ----
    {
      const int cc = tid;
      if (cc < p.VQN) {
        ulonglong2 cb[16];
        const ulonglong2* cp =
            reinterpret_cast<const ulonglong2*>(p.codebook + (size_t)cc * 64);
        #pragma unroll
        for (int q = 0; q < 16; q++) cb[q] = __ldg(cp + q);
        unsigned long long cn2 = 0ull;
        #pragma unroll
        for (int q = 0; q < 16; q++) { fma2(cn2, cb[q].x, cb[q].x); fma2(cn2, cb[q].y, cb[q].y); }
        const float cn = lo32(cn2) + hi32(cn2);
        #pragma unroll
        for (int r = 0; r < RB; r++) {
          const ulonglong2* A2 = reinterpret_cast<const ulonglong2*>(sm.A[r]);
          unsigned long long dot2 = 0ull;
          #pragma unroll
          for (int q = 0; q < 16; q++) {
            const ulonglong2 a = A2[q];           // broadcast LDS.128
            fma2(dot2, a.x, cb[q].x);
            fma2(dot2, a.y, cb[q].y);
          }
          const float dot = lo32(dot2) + hi32(dot2);
          sm.dist[r][cc] = sm.znorm[r] - 2.f * dot + cn;
        }
      }
    }
    __syncthreads();

    // ---- argmin per row (warp r of 16), lexicographic (d, idx) ----
    const int warp = tid >> 5, lane = tid & 31;
    {
      const int r = warp;
      float best = 3.4e38f; int bi = 0;
      for (int cc = lane; cc < p.VQN; cc += 32) {
        const float d = sm.dist[r][cc];
        if (d < best) { best = d; bi = cc; }
      }
      #pragma unroll
      for (int o = 16; o; o >>= 1) {
        const float ob = __shfl_down_sync(0xffffffffu, best, o);
        const int   oi = __shfl_down_sync(0xffffffffu, bi,   o);
        if (ob < best || (ob == best && oi < bi)) { best = ob; bi = oi; }
      }
      bi = __shfl_sync(0xffffffffu, bi, 0);
      float ls = 0.f;
      for (int k = lane; k < 64; k += 32) {
        const float dq = __ldg(p.codebook + (size_t)bi * 64 + k) - sm.A[r][k];
        ls = fmaf(dq, dq, ls);
      }
      #pragma unroll
      for (int o = 16; o; o >>= 1) ls += __shfl_down_sync(0xffffffffu, ls, o);
      if (lane == 0 && c0 + r < p.NC) {
        g_idx_cls[c0 + r]  = bi;
        g_loss_cls[c0 + r] = ls;
      }
    }
  } else {
    // ================= HEAD PATH: 16 codes =================
    const int q0 = ((int)blockIdx.x - p.nClsBlk) * RB;

    if (tid < RB * 16) {     // gather 16 codebook rows
      const int r = tid >> 4, col = tid & 15;
      reinterpret_cast<float4*>(sm.A[r])[col] =
          __ldg(reinterpret_cast<const float4*>(p.codebook + (size_t)(q0 + r) * 64) + col);
    }
    __syncthreads();

    layerW<64, 128, 2>(sm.A,  p.Wa,  p.ba,  nullptr, g_tbl_actor, q0, sm);
    layerW<64, 128, 3>(sm.A,  p.Ws,  p.bs,  nullptr, g_tbl_scale, q0, sm);
    layerW<64, 128, 2>(sm.A,  p.Wc1, p.bc1, sm.Bb,   nullptr, 0, sm);
    layerW<128, 128, 2>(sm.Bb, p.Wc2, p.bc2, sm.A,   nullptr, 0, sm);
    layerW<128, 32, 2>(sm.A,  p.Wc3, p.bc3, sm.Bb,   nullptr, 0, sm);

    if (tid < RB) {
      float s = __ldg(p.bc4);
      #pragma unroll
      for (int k = 0; k < 32; k++) s = fmaf(sm.Bb[tid][k], __ldg(p.Wc4 + k), s);
      g_tbl_crit[q0 + tid] = s;
    }
  }
}

// ==== gather (split version, measured 24.9-25.0 us): ====
// 1024 blocks = 512 row-tiles x {actor, scale}. Actor blocks also write
// idx/critic and the per-tile loss partial (same 256-row grouping as the
// proven kernel -> loss bit-identical).
__global__ void __launch_bounds__(NTG) acsq_gather(Params p, float scale)
{
  __shared__ int   codes[NTG];
  __shared__ float red[8];
  __shared__ float s[NTG];
  __shared__ bool  lastblk;
  const int tid = threadIdx.x;
  const int tbl = blockIdx.x & 1;                // 0 = actor, 1 = scale
  const int rt  = blockIdx.x >> 1;               // row tile
  const size_t row0 = (size_t)rt * NTG;
  const size_t b = row0 + tid;

  if (tid == 0) lastblk = false;

  float lp = 0.f;
  int code = 0;
  if (b < (size_t)p.B) {
    const int o = p.obs[b];
    code = g_idx_cls[o];
    if (tbl == 0) {
      lp = g_loss_cls[o];
      p.out_idx[b]    = (float)code;
      p.out_critic[b] = g_tbl_crit[code];
    }
  }
  codes[tid] = code;

  if (tbl == 0) {
    #pragma unroll
    for (int o = 16; o; o >>= 1) lp += __shfl_down_sync(0xffffffffu, lp, o);
    if ((tid & 31) == 0) red[tid >> 5] = lp;
  }
  __syncthreads();
  if (tbl == 0 && tid == 0) {
    float t = 0.f;
    #pragma unroll
    for (int w = 0; w < 8; w++) t += red[w];
    g_partials[rt] = t;
    __threadfence();
    lastblk = (atomicAdd(&g_ticket, 1u) == (unsigned)(p.gtiles - 1));
  }

  const float4* ta = reinterpret_cast<const float4*>(tbl ? g_tbl_scale : g_tbl_actor);
  float4* od = reinterpret_cast<float4*>(tbl ? p.out_scale : p.out_actor);
  __syncthreads();
  #pragma unroll 4
  for (int i = tid; i < NTG * 32; i += NTG) {
    const int r = i >> 5, cc = i & 31;
    if (row0 + r < (size_t)p.B) {
      const int cd = codes[r];
      od[(row0 + r) * 32 + cc] = ta[cd * 32 + cc];
    }
  }

  if (lastblk) {
    float v = 0.f;
    for (int i = tid; i < p.gtiles; i += NTG) v += g_partials[i];  // fixed order
    s[tid] = v;
    __syncthreads();
    for (int o = NTG / 2; o > 0; o >>= 1) {
      if (tid < o) s[tid] += s[tid + o];
      __syncthreads();
    }
    if (tid == 0) { *p.out_loss = s[0] * scale; g_ticket = 0u; }
  }
}

extern "C" void kernel_launch(void* const* d_in, const int* in_sizes, int n_in,
                              void* d_out, int out_size)
{
  Params p;
  p.obs      = (const int*)d_in[0];
  p.embed    = (const float*)d_in[1];
  p.W1  = (const float*)d_in[2];  p.b1  = (const float*)d_in[3];
  p.W2  = (const float*)d_in[4];  p.b2  = (const float*)d_in[5];
  p.W3  = (const float*)d_in[6];  p.b3  = (const float*)d_in[7];
  p.Wp  = (const float*)d_in[8];  p.bp  = (const float*)d_in[9];
  p.codebook = (const float*)d_in[10];
  p.Wa  = (const float*)d_in[11]; p.ba  = (const float*)d_in[12];
  p.Ws  = (const float*)d_in[13]; p.bs  = (const float*)d_in[14];
  p.Wc1 = (const float*)d_in[15]; p.bc1 = (const float*)d_in[16];
  p.Wc2 = (const float*)d_in[17]; p.bc2 = (const float*)d_in[18];
  p.Wc3 = (const float*)d_in[19]; p.bc3 = (const float*)d_in[20];
  p.Wc4 = (const float*)d_in[21]; p.bc4 = (const float*)d_in[22];

  const int B   = in_sizes[0];
  const int NC  = in_sizes[1] / 128;   // embed is [NC, 128]
  const int VQN = in_sizes[10] / 64;   // codebook is [VQN, 64]
  p.B = B; p.NC = NC; p.VQN = VQN;
  p.nClsBlk = (NC + RB - 1) / RB;      // 63
  p.gtiles  = (B + NTG - 1) / NTG;     // 512

  float* out = (float*)d_out;
  p.out_actor  = out;                                  // [B,128]
  p.out_scale  = out + (size_t)B * 128;                // [B,128]
  p.out_critic = out + (size_t)2 * B * 128;            // [B]
  p.out_loss   = out + (size_t)2 * B * 128 + B;        // scalar
  p.out_idx    = out + (size_t)2 * B * 128 + B + 1;    // [B] as float

  const int headBlk = (VQN + RB - 1) / RB;             // 32
  cudaFuncSetAttribute(acsq_ab, cudaFuncAttributeMaxDynamicSharedMemorySize,
                       (int)sizeof(SmemAB));
  acsq_ab<<<p.nClsBlk + headBlk, NTA, sizeof(SmemAB)>>>(p);
  acsq_gather<<<p.gtiles * 2, NTG>>>(p, 1.25f / ((float)B * 64.f));
}